// round 14
// baseline (speedup 1.0000x reference)
#include <cuda_runtime.h>
#include <cuda_bf16.h>
#include <math.h>
#include <math_constants.h>
#include <cstdint>

// Problem shapes (fixed by the dataset)
#define B_ 64
#define C_ 5
#define H_ 50
#define S_ 32
#define E_ 768
#define D_ 768
#define K_ 5
#define CROWS (B_*C_)            // 320 candidate rows
#define HROWS (B_*H_)            // 3200 history rows
#define ROWS (CROWS + HROWS)     // 3520 total projected rows
#define ROWSP 3584               // padded to multiple of 128
#define SEL (CROWS*K_)           // 1600 gather selections
#define SE (S_*E_)               // 24576 floats per selection

// Hybrid GEMM row partition
#define MT_ROWS 2048                     // rows via tensor path
#define MF_ROWS (ROWSP - MT_ROWS)        // 1536 rows via FFMA
#define NCTA_T4 ((MT_ROWS/64) * (D_/64)) // 384 tensor CTAs (64x64)
#define NCTA_F  ((MF_ROWS/64) * (D_/64)) // 288 FFMA CTAs (64x64)
#define NCTA_ALL (NCTA_T4 + NCTA_F)      // 672 = 96*7

// ---------------- scratch (static device globals; no allocation) -----------
__device__ __nv_bfloat16 g_Xs[3][(size_t)MT_ROWS * D_];  // X split limbs (tensor rows only)
__device__ __nv_bfloat16 g_Ws[3][(size_t)D_ * D_];       // W split limbs
__device__ float  g_P[(size_t)ROWSP * D_];               // projected rows (padded)
__device__ double g_attn[CROWS * H_];                    // masked attention scores
__device__ int    g_idx[SEL];                            // top-K indices per (b,c)

// ======================= small helpers =====================================
__device__ __forceinline__ uint32_t smem_u32(const void* p) {
    uint32_t a;
    asm("{ .reg .u64 t; cvta.to.shared.u64 t, %1; cvt.u32.u64 %0, t; }" : "=r"(a) : "l"(p));
    return a;
}
__device__ __forceinline__ void cp_async16(uint32_t dst, const void* src) {
    asm volatile("cp.async.cg.shared.global [%0], [%1], 16;"
                 :: "r"(dst), "l"(__cvta_generic_to_global(src)));
}
#define CP_COMMIT() asm volatile("cp.async.commit_group;" ::: "memory")
#define CP_WAIT(n)  asm volatile("cp.async.wait_group %0;" :: "n"(n) : "memory")

__device__ __forceinline__ void ldsm4(uint32_t addr, uint32_t& r0, uint32_t& r1,
                                      uint32_t& r2, uint32_t& r3) {
    asm volatile("ldmatrix.sync.aligned.m8n8.x4.shared.b16 {%0,%1,%2,%3}, [%4];"
                 : "=r"(r0), "=r"(r1), "=r"(r2), "=r"(r3) : "r"(addr));
}
__device__ __forceinline__ void mma16816(float* c, const uint32_t* a,
                                         uint32_t b0, uint32_t b1) {
    asm volatile("mma.sync.aligned.m16n8k16.row.col.f32.bf16.bf16.f32 "
                 "{%0,%1,%2,%3}, {%4,%5,%6,%7}, {%8,%9}, {%0,%1,%2,%3};"
                 : "+f"(c[0]), "+f"(c[1]), "+f"(c[2]), "+f"(c[3])
                 : "r"(a[0]), "r"(a[1]), "r"(a[2]), "r"(a[3]), "r"(b0), "r"(b1));
}
__device__ __forceinline__ uint32_t pack_bf2(float lo, float hi) {
    __nv_bfloat162 t = __floats2bfloat162_rn(lo, hi);
    return *(uint32_t*)&t;
}
__device__ __forceinline__ float bf_trunc(float v, float& rem) {
    __nv_bfloat16 b = __float2bfloat16(v);
    float f = __bfloat162float(b);
    rem = v - f;
    return f;
}

// ================== 0a) split X fp32 -> 3 bf16 limbs =======================
__global__ void splitX_kernel(const float* __restrict__ cdd,
                              const float* __restrict__ his) {
    const size_t NX4 = (size_t)MT_ROWS * D_ / 4;
    size_t i = (size_t)blockIdx.x * blockDim.x + threadIdx.x;
    if (i >= NX4) return;
    const size_t base = i * 4;
    const size_t row = base / D_;
    float4 v = (row < CROWS) ? *(const float4*)(cdd + base)
                             : *(const float4*)(his + (base - (size_t)CROWS * D_));
    float f[4] = {v.x, v.y, v.z, v.w};
    #pragma unroll
    for (int lb = 0; lb < 3; lb++) {
        float t[4];
        #pragma unroll
        for (int j = 0; j < 4; j++) { float r; t[j] = bf_trunc(f[j], r); f[j] = r; }
        *(uint2*)&g_Xs[lb][base] = make_uint2(pack_bf2(t[0], t[1]), pack_bf2(t[2], t[3]));
    }
}

// ================== 0b) split W fp32 -> 3 bf16 limbs =======================
__global__ void splitW_kernel(const float* __restrict__ W) {
    const size_t NW4 = (size_t)D_ * D_ / 4;
    size_t i = (size_t)blockIdx.x * blockDim.x + threadIdx.x;
    if (i >= NW4) return;
    const size_t base = i * 4;
    float4 v = *(const float4*)(W + base);
    float f[4] = {v.x, v.y, v.z, v.w};
    #pragma unroll
    for (int lb = 0; lb < 3; lb++) {
        float t[4];
        #pragma unroll
        for (int j = 0; j < 4; j++) { float r; t[j] = bf_trunc(f[j], r); f[j] = r; }
        *(uint2*)&g_Ws[lb][base] = make_uint2(pack_bf2(t[0], t[1]), pack_bf2(t[2], t[3]));
    }
}

// =========== 1) HYBRID GEMM, occ 4: tensor 64x64 (R9) + FFMA 64x64 (R1) ====
// Tensor: EXACT R9 body (bf16x3, 6 products, KC=32, SSTRIDE=40) — proven.
// FFMA:   EXACT R1 body (fp32 SGEMM, BK=16) — proven.
// Interleaved grid: bid%7<4 -> tensor (384), else FFMA (288). One wave occ4.
#define NPROD 6
#define KC 32
#define NKT (D_ / KC)                    // 24
#define NIT (NPROD * NKT)                // 144
#define SSTRIDE 40

__constant__ int c_pa[NPROD] = {0, 0, 1, 0, 2, 1};
__constant__ int c_pb[NPROD] = {0, 1, 0, 2, 0, 1};

#define SM_BYTES 20480

__global__ void __launch_bounds__(256, 4)
gemm_hybrid(const float* __restrict__ cdd, const float* __restrict__ his,
            const float* __restrict__ W, const float* __restrict__ bias) {
    __shared__ __align__(16) unsigned char smraw[SM_BYTES];

    const int tid = threadIdx.x;
    const int grp = blockIdx.x / 7, sub = blockIdx.x % 7;

    if (sub < 4) {
        // ---------- tensor path: EXACT R9 64x64 body, rows 0..2047 ---------
        const int ti = grp * 4 + sub;                  // 0..383
        const int m0 = (ti % (MT_ROWS / 64)) * 64;     // 32 m-tiles
        const int n0 = (ti / (MT_ROWS / 64)) * 64;     // 12 n-tiles
        const int wid = tid >> 5, lane = tid & 31;
        const int wm = (wid >> 1) * 16;
        const int wn = (wid & 1) * 32;

        __nv_bfloat16 (*sm)[128 * SSTRIDE] = (__nv_bfloat16(*)[128 * SSTRIDE])smraw;
        const uint32_t smb[2] = { smem_u32(&sm[0][0]), smem_u32(&sm[1][0]) };
        const int lrow = lane & 15;
        const int lcol = (lane >> 4) << 3;
        const int jrow = tid >> 1;
        const int jc0  = (tid & 1) * 2;

        float acc[4][4];
        #pragma unroll
        for (int j = 0; j < 4; j++)
            #pragma unroll
            for (int v = 0; v < 4; v++) acc[j][v] = 0.f;

        auto load_tile = [&](int it, int buf) {
            const int p  = it / NKT;
            const int kb = (it % NKT) * KC;
            const __nv_bfloat16* src = (jrow < 64)
                ? g_Xs[c_pa[p]] + (size_t)(m0 + jrow) * D_ + kb
                : g_Ws[c_pb[p]] + (size_t)(n0 + jrow - 64) * D_ + kb;
            #pragma unroll
            for (int h = 0; h < 2; h++) {
                const int cq = jc0 + h;
                cp_async16(smb[buf] + (uint32_t)(jrow * SSTRIDE + cq * 8) * 2, src + cq * 8);
            }
            CP_COMMIT();
        };

        load_tile(0, 0);

        for (int it = 0; it < NIT; it++) {
            const int buf = it & 1;
            if (it + 1 < NIT) { load_tile(it + 1, buf ^ 1); CP_WAIT(1); }
            else              { CP_WAIT(0); }
            __syncthreads();

            #pragma unroll
            for (int kh = 0; kh < 2; kh++) {
                const int kb = kh * 16;
                uint32_t a[4];
                {
                    uint32_t addr = smb[buf] +
                        (uint32_t)((wm + lrow) * SSTRIDE + kb + lcol) * 2;
                    ldsm4(addr, a[0], a[1], a[2], a[3]);
                }
                uint32_t bfr[2][4];
                #pragma unroll
                for (int nb = 0; nb < 2; nb++) {
                    uint32_t addr = smb[buf] +
                        (uint32_t)((64 + wn + nb * 16 + lrow) * SSTRIDE + kb + lcol) * 2;
                    ldsm4(addr, bfr[nb][0], bfr[nb][1], bfr[nb][2], bfr[nb][3]);
                }
                #pragma unroll
                for (int oct = 0; oct < 4; oct++) {
                    const int nb = oct >> 1, par = oct & 1;
                    mma16816(acc[oct], a, bfr[nb][par], bfr[nb][par + 2]);
                }
            }
            __syncthreads();
        }

        const int g = lane >> 2, t = lane & 3;
        #pragma unroll
        for (int oct = 0; oct < 4; oct++) {
            const int col = n0 + wn + oct * 8 + 2 * t;
            const float b0 = __ldg(bias + col), b1 = __ldg(bias + col + 1);
            const int r0 = m0 + wm + g;
            float2 v0 = { acc[oct][0] + b0, acc[oct][1] + b1 };
            float2 v1 = { acc[oct][2] + b0, acc[oct][3] + b1 };
            *(float2*)(g_P + (size_t)r0 * D_ + col)       = v0;
            *(float2*)(g_P + (size_t)(r0 + 8) * D_ + col) = v1;
        }
    } else {
        // ---------- FFMA path: EXACT R1 body, rows 2048..3583 --------------
        const int fi = grp * 3 + (sub - 4);            // 0..287
        const int m0 = MT_ROWS + (fi % (MF_ROWS / 64)) * 64;
        const int n0 = (fi / (MF_ROWS / 64)) * 64;

        float (*As)[64] = (float(*)[64])smraw;          // [16][64]
        float (*Bs)[64] = (float(*)[64])(smraw + 4096); // [16][64]

        const int tx = tid & 15, ty = tid >> 4;
        const int lrow = tid >> 2;
        const int kq   = (tid & 3) << 2;
        const int gr   = m0 + lrow;
        const float* xsrc = (gr < CROWS) ? (cdd + (size_t)gr * D_)
                         : (gr < ROWS)   ? (his + (size_t)(gr - CROWS) * D_)
                                         : his;
        const float* wsrc = W + (size_t)(n0 + lrow) * D_;

        float acc[4][4] = {};

        for (int k0 = 0; k0 < D_; k0 += 16) {
            float4 a = *(const float4*)(xsrc + k0 + kq);
            float4 b = *(const float4*)(wsrc + k0 + kq);
            As[kq+0][lrow] = a.x; As[kq+1][lrow] = a.y;
            As[kq+2][lrow] = a.z; As[kq+3][lrow] = a.w;
            Bs[kq+0][lrow] = b.x; Bs[kq+1][lrow] = b.y;
            Bs[kq+2][lrow] = b.z; Bs[kq+3][lrow] = b.w;
            __syncthreads();

            #pragma unroll
            for (int kk = 0; kk < 16; kk++) {
                float4 av = *(const float4*)&As[kk][ty << 2];
                float4 bv = *(const float4*)&Bs[kk][tx << 2];
                float aa[4] = {av.x, av.y, av.z, av.w};
                float bb[4] = {bv.x, bv.y, bv.z, bv.w};
                #pragma unroll
                for (int i = 0; i < 4; i++)
                    #pragma unroll
                    for (int j = 0; j < 4; j++)
                        acc[i][j] = fmaf(aa[i], bb[j], acc[i][j]);
            }
            __syncthreads();
        }

        #pragma unroll
        for (int i = 0; i < 4; i++) {
            const int r = m0 + (ty << 2) + i;
            #pragma unroll
            for (int j = 0; j < 4; j++) {
                const int n = n0 + (tx << 2) + j;
                g_P[(size_t)r * D_ + n] = acc[i][j] + bias[n];
            }
        }
    }
}

// =============== compensated fp32 accumulation (TwoProd+TwoSum) ============
__device__ __forceinline__ void dot2_acc(float a, float b, float& s, float& c) {
    float p  = __fmul_rn(a, b);
    float e  = __fmaf_rn(a, b, -p);
    float t  = __fadd_rn(s, p);
    float bp = __fsub_rn(t, s);
    float e2 = __fadd_rn(__fsub_rn(s, __fsub_rn(t, bp)), __fsub_rn(p, bp));
    s = t;
    c = __fadd_rn(c, __fadd_rn(e, e2));
}

// ---------- 2+3) attention scores, block (b, part); ONE h per warp ---------
// 320 threads = 10 warps; warp w handles h = part*10 + w exactly once.
// Per-(c,h) arithmetic bit-identical to R12.
#define HSPLIT 5
#define HPER (H_ / HSPLIT)               // 10

__global__ void __launch_bounds__(320)
attn_score(const int* __restrict__ his_mask) {
    const int b    = blockIdx.x;
    const int part = blockIdx.y;
    const int tid = threadIdx.x;
    const int w = tid >> 5, l = tid & 31;

    __shared__ float  cand[C_][D_];      // 15 KB
    __shared__ double invc[C_];

    for (int i = tid; i < C_ * (D_ / 4); i += 320) {
        const int c = i / (D_ / 4), j = i % (D_ / 4);
        ((float4*)cand[c])[j] = ((const float4*)(g_P + (size_t)(b * C_ + c) * D_))[j];
    }
    __syncthreads();

    if (w < C_) {
        float s = 0.f, cc = 0.f;
        for (int k = l; k < D_; k += 32) { float v = cand[w][k]; dot2_acc(v, v, s, cc); }
        double d = (double)s + (double)cc;
        #pragma unroll
        for (int o = 16; o; o >>= 1) d += __shfl_down_sync(0xffffffffu, d, o);
        if (l == 0) invc[w] = 1.0 / fmax(sqrt(d), 1e-12);
    }
    __syncthreads();

    {
        const int h = part * HPER + w;   // one h per warp, w in 0..9
        const float4* ph = (const float4*)(g_P + (size_t)(CROWS + b * H_ + h) * D_);
        float s[C_] = {}, cc[C_] = {};
        float sn = 0.f, cn = 0.f;
        #pragma unroll
        for (int j = 0; j < D_ / 128; j++) {
            const int idx = l + 32 * j;
            const float4 v = ph[idx];
            dot2_acc(v.x, v.x, sn, cn); dot2_acc(v.y, v.y, sn, cn);
            dot2_acc(v.z, v.z, sn, cn); dot2_acc(v.w, v.w, sn, cn);
            #pragma unroll
            for (int c = 0; c < C_; c++) {
                const float4 cv = ((const float4*)cand[c])[idx];
                dot2_acc(v.x, cv.x, s[c], cc[c]); dot2_acc(v.y, cv.y, s[c], cc[c]);
                dot2_acc(v.z, cv.z, s[c], cc[c]); dot2_acc(v.w, cv.w, s[c], cc[c]);
            }
        }
        double dn = (double)sn + (double)cn;
        double dc[C_];
        #pragma unroll
        for (int c = 0; c < C_; c++) dc[c] = (double)s[c] + (double)cc[c];
        #pragma unroll
        for (int o = 16; o; o >>= 1) {
            dn += __shfl_down_sync(0xffffffffu, dn, o);
            #pragma unroll
            for (int c = 0; c < C_; c++) dc[c] += __shfl_down_sync(0xffffffffu, dc[c], o);
        }
        if (l == 0) {
            const bool valid = (his_mask[b * H_ + h] != 0) || (h < K_);
            const double invh = 1.0 / fmax(sqrt(dn), 1e-12);
            #pragma unroll
            for (int c = 0; c < C_; c++)
                g_attn[(b * C_ + c) * H_ + h] =
                    valid ? dc[c] * invc[c] * invh : -CUDART_INF;
        }
    }
}

// ---------------- 4) top-K (exact R1 kernel: one warp per (b,c)) -----------
__global__ void topk_kernel() {
    const int gw = (blockIdx.x * blockDim.x + threadIdx.x) >> 5;
    const int l  = threadIdx.x & 31;
    if (gw >= CROWS) return;
    const double* a = g_attn + (size_t)gw * H_;

    double v0 = (l      < H_) ? a[l]      : -CUDART_INF;
    double v1 = (l + 32 < H_) ? a[l + 32] : -CUDART_INF;
    bool used0 = false, used1 = false;

    for (int k = 0; k < K_; k++) {
        double bv = -CUDART_INF;
        int    bi = 1 << 30;
        if (!used1)                           { bv = v1; bi = l + 32; }
        if (!used0 && (used1 || v0 >= v1))    { bv = v0; bi = l; }
        #pragma unroll
        for (int o = 16; o; o >>= 1) {
            double ov = __shfl_down_sync(0xffffffffu, bv, o);
            int    oi = __shfl_down_sync(0xffffffffu, bi, o);
            if (ov > bv || (ov == bv && oi < bi)) { bv = ov; bi = oi; }
        }
        bi = __shfl_sync(0xffffffffu, bi, 0);
        if (l == 0) g_idx[gw * K_ + k] = bi;
        if (bi == l)      used0 = true;
        if (bi == l + 32) used1 = true;
    }
}

// ------- 5+6) embedding gather + fused mask gather (bandwidth-bound) -------
__global__ void gather_emb(const float* __restrict__ emb,
                           const int* __restrict__ am,
                           float* __restrict__ out) {
    const int sel  = blockIdx.x >> 3;
    const int part = blockIdx.x & 7;
    const int b    = sel / (C_ * K_);
    const int idx  = g_idx[sel];
    const float4* src = (const float4*)(emb + ((size_t)b * H_ + idx) * SE);
    float4*       dst = (float4*)(out + (size_t)sel * SE);
    const int base = part * 768;
    #pragma unroll
    for (int i = 0; i < 3; i++) {
        const int o = base + threadIdx.x + i * 256;
        __stcs(dst + o, src[o]);
    }
    if (part == 7 && threadIdx.x < S_) {
        float* outm = out + (size_t)SEL * SE;
        outm[sel * S_ + threadIdx.x] =
            (float)am[((size_t)b * H_ + idx) * S_ + threadIdx.x];
    }
}

// ---------------------------------------------------------------------------
extern "C" void kernel_launch(void* const* d_in, const int* in_sizes, int n_in,
                              void* d_out, int out_size) {
    const float* cdd  = (const float*)d_in[0];   // [B,C,D]
    const float* his  = (const float*)d_in[1];   // [B,H,D]
    const float* emb  = (const float*)d_in[2];   // [B,H,S,E]
    const int*   am   = (const int*)  d_in[3];   // [B,H,S]
    const int*   hm   = (const int*)  d_in[4];   // [B,H,1]
    const float* W    = (const float*)d_in[5];   // [D,D]
    const float* bias = (const float*)d_in[6];   // [D]
    float* out = (float*)d_out;

    const size_t NX4 = (size_t)MT_ROWS * D_ / 4;
    const size_t NW4 = (size_t)D_ * D_ / 4;
    splitX_kernel<<<(unsigned)((NX4 + 255) / 256), 256>>>(cdd, his);
    splitW_kernel<<<(unsigned)((NW4 + 255) / 256), 256>>>(W);
    gemm_hybrid<<<NCTA_ALL, 256>>>(cdd, his, W, bias);
    attn_score<<<dim3(B_, HSPLIT), 320>>>(hm);
    topk_kernel<<<(CROWS * 32 + 255) / 256, 256>>>();
    gather_emb<<<SEL * 8, 256>>>(emb, am, out);
}

// round 15
// speedup vs baseline: 1.0012x; 1.0012x over previous
#include <cuda_runtime.h>
#include <cuda_bf16.h>
#include <math.h>
#include <math_constants.h>
#include <cstdint>

// Problem shapes (fixed by the dataset)
#define B_ 64
#define C_ 5
#define H_ 50
#define S_ 32
#define E_ 768
#define D_ 768
#define K_ 5
#define CROWS (B_*C_)            // 320 candidate rows
#define HROWS (B_*H_)            // 3200 history rows
#define ROWS (CROWS + HROWS)     // 3520 total projected rows
#define ROWSP 3584               // padded to multiple of 128
#define SEL (CROWS*K_)           // 1600 gather selections
#define SE (S_*E_)               // 24576 floats per selection

// Hybrid GEMM row partition
#define MT_ROWS 2048                     // rows via tensor path
#define MF_ROWS (ROWSP - MT_ROWS)        // 1536 rows via FFMA
#define NCTA_T4 ((MT_ROWS/64) * (D_/64)) // 384 tensor CTAs (64x64)
#define NCTA_F  ((MF_ROWS/64) * (D_/64)) // 288 FFMA CTAs (64x64)
#define NCTA_ALL (NCTA_T4 + NCTA_F)      // 672 = 96*7

// ---------------- scratch (static device globals; no allocation) -----------
__device__ __nv_bfloat16 g_Xs[3][(size_t)MT_ROWS * D_];  // X split limbs (tensor rows only)
__device__ __nv_bfloat16 g_Ws[3][(size_t)D_ * D_];       // W split limbs
__device__ float  g_P[(size_t)ROWSP * D_];               // projected rows (padded)
__device__ double g_attn[CROWS * H_];                    // masked attention scores
__device__ int    g_idx[SEL];                            // top-K indices per (b,c)

// ======================= small helpers =====================================
__device__ __forceinline__ uint32_t smem_u32(const void* p) {
    uint32_t a;
    asm("{ .reg .u64 t; cvta.to.shared.u64 t, %1; cvt.u32.u64 %0, t; }" : "=r"(a) : "l"(p));
    return a;
}
__device__ __forceinline__ void cp_async16(uint32_t dst, const void* src) {
    asm volatile("cp.async.cg.shared.global [%0], [%1], 16;"
                 :: "r"(dst), "l"(__cvta_generic_to_global(src)));
}
#define CP_COMMIT() asm volatile("cp.async.commit_group;" ::: "memory")
#define CP_WAIT(n)  asm volatile("cp.async.wait_group %0;" :: "n"(n) : "memory")

__device__ __forceinline__ void ldsm4(uint32_t addr, uint32_t& r0, uint32_t& r1,
                                      uint32_t& r2, uint32_t& r3) {
    asm volatile("ldmatrix.sync.aligned.m8n8.x4.shared.b16 {%0,%1,%2,%3}, [%4];"
                 : "=r"(r0), "=r"(r1), "=r"(r2), "=r"(r3) : "r"(addr));
}
__device__ __forceinline__ void mma16816(float* c, const uint32_t* a,
                                         uint32_t b0, uint32_t b1) {
    asm volatile("mma.sync.aligned.m16n8k16.row.col.f32.bf16.bf16.f32 "
                 "{%0,%1,%2,%3}, {%4,%5,%6,%7}, {%8,%9}, {%0,%1,%2,%3};"
                 : "+f"(c[0]), "+f"(c[1]), "+f"(c[2]), "+f"(c[3])
                 : "r"(a[0]), "r"(a[1]), "r"(a[2]), "r"(a[3]), "r"(b0), "r"(b1));
}
__device__ __forceinline__ uint32_t pack_bf2(float lo, float hi) {
    __nv_bfloat162 t = __floats2bfloat162_rn(lo, hi);
    return *(uint32_t*)&t;
}
__device__ __forceinline__ float bf_trunc(float v, float& rem) {
    __nv_bfloat16 b = __float2bfloat16(v);
    float f = __bfloat162float(b);
    rem = v - f;
    return f;
}
// packed f32x2 helpers (sm_10x): componentwise rn FMA — bit-identical to fmaf
__device__ __forceinline__ unsigned long long dup_f32x2(float x) {
    unsigned long long r;
    asm("mov.b64 %0, {%1, %1};" : "=l"(r) : "f"(x));
    return r;
}
__device__ __forceinline__ void fma_f32x2(unsigned long long& acc,
                                          unsigned long long a,
                                          unsigned long long b) {
    asm("fma.rn.f32x2 %0, %1, %2, %0;" : "+l"(acc) : "l"(a), "l"(b));
}
__device__ __forceinline__ float2 unpack_f32x2(unsigned long long v) {
    float2 r;
    asm("mov.b64 {%0, %1}, %2;" : "=f"(r.x), "=f"(r.y) : "l"(v));
    return r;
}

// ================== 0a) split X fp32 -> 3 bf16 limbs =======================
__global__ void splitX_kernel(const float* __restrict__ cdd,
                              const float* __restrict__ his) {
    const size_t NX4 = (size_t)MT_ROWS * D_ / 4;
    size_t i = (size_t)blockIdx.x * blockDim.x + threadIdx.x;
    if (i >= NX4) return;
    const size_t base = i * 4;
    const size_t row = base / D_;
    float4 v = (row < CROWS) ? *(const float4*)(cdd + base)
                             : *(const float4*)(his + (base - (size_t)CROWS * D_));
    float f[4] = {v.x, v.y, v.z, v.w};
    #pragma unroll
    for (int lb = 0; lb < 3; lb++) {
        float t[4];
        #pragma unroll
        for (int j = 0; j < 4; j++) { float r; t[j] = bf_trunc(f[j], r); f[j] = r; }
        *(uint2*)&g_Xs[lb][base] = make_uint2(pack_bf2(t[0], t[1]), pack_bf2(t[2], t[3]));
    }
}

// ================== 0b) split W fp32 -> 3 bf16 limbs =======================
__global__ void splitW_kernel(const float* __restrict__ W) {
    const size_t NW4 = (size_t)D_ * D_ / 4;
    size_t i = (size_t)blockIdx.x * blockDim.x + threadIdx.x;
    if (i >= NW4) return;
    const size_t base = i * 4;
    float4 v = *(const float4*)(W + base);
    float f[4] = {v.x, v.y, v.z, v.w};
    #pragma unroll
    for (int lb = 0; lb < 3; lb++) {
        float t[4];
        #pragma unroll
        for (int j = 0; j < 4; j++) { float r; t[j] = bf_trunc(f[j], r); f[j] = r; }
        *(uint2*)&g_Ws[lb][base] = make_uint2(pack_bf2(t[0], t[1]), pack_bf2(t[2], t[3]));
    }
}

// =========== 1) HYBRID GEMM, occ 4: tensor 64x64 (R9) + FFMA2 64x64 ========
// Tensor: EXACT R9/R13 body (bf16x3, 6 products, KC=32, SSTRIDE=40).
// FFMA:   R1 body with packed fma.rn.f32x2 — bit-identical values, ~40% fewer
//         issue slots, to stop starving co-resident tensor warps.
#define NPROD 6
#define KC 32
#define NKT (D_ / KC)                    // 24
#define NIT (NPROD * NKT)                // 144
#define SSTRIDE 40

__constant__ int c_pa[NPROD] = {0, 0, 1, 0, 2, 1};
__constant__ int c_pb[NPROD] = {0, 1, 0, 2, 0, 1};

#define SM_BYTES 20480

__global__ void __launch_bounds__(256, 4)
gemm_hybrid(const float* __restrict__ cdd, const float* __restrict__ his,
            const float* __restrict__ W, const float* __restrict__ bias) {
    __shared__ __align__(16) unsigned char smraw[SM_BYTES];

    const int tid = threadIdx.x;
    const int grp = blockIdx.x / 7, sub = blockIdx.x % 7;

    if (sub < 4) {
        // ---------- tensor path: EXACT R9/R13 64x64 body, rows 0..2047 -----
        const int ti = grp * 4 + sub;                  // 0..383
        const int m0 = (ti % (MT_ROWS / 64)) * 64;     // 32 m-tiles
        const int n0 = (ti / (MT_ROWS / 64)) * 64;     // 12 n-tiles
        const int wid = tid >> 5, lane = tid & 31;
        const int wm = (wid >> 1) * 16;
        const int wn = (wid & 1) * 32;

        __nv_bfloat16 (*sm)[128 * SSTRIDE] = (__nv_bfloat16(*)[128 * SSTRIDE])smraw;
        const uint32_t smb[2] = { smem_u32(&sm[0][0]), smem_u32(&sm[1][0]) };
        const int lrow = lane & 15;
        const int lcol = (lane >> 4) << 3;
        const int jrow = tid >> 1;
        const int jc0  = (tid & 1) * 2;

        float acc[4][4];
        #pragma unroll
        for (int j = 0; j < 4; j++)
            #pragma unroll
            for (int v = 0; v < 4; v++) acc[j][v] = 0.f;

        auto load_tile = [&](int it, int buf) {
            const int p  = it / NKT;
            const int kb = (it % NKT) * KC;
            const __nv_bfloat16* src = (jrow < 64)
                ? g_Xs[c_pa[p]] + (size_t)(m0 + jrow) * D_ + kb
                : g_Ws[c_pb[p]] + (size_t)(n0 + jrow - 64) * D_ + kb;
            #pragma unroll
            for (int h = 0; h < 2; h++) {
                const int cq = jc0 + h;
                cp_async16(smb[buf] + (uint32_t)(jrow * SSTRIDE + cq * 8) * 2, src + cq * 8);
            }
            CP_COMMIT();
        };

        load_tile(0, 0);

        for (int it = 0; it < NIT; it++) {
            const int buf = it & 1;
            if (it + 1 < NIT) { load_tile(it + 1, buf ^ 1); CP_WAIT(1); }
            else              { CP_WAIT(0); }
            __syncthreads();

            #pragma unroll
            for (int kh = 0; kh < 2; kh++) {
                const int kb = kh * 16;
                uint32_t a[4];
                {
                    uint32_t addr = smb[buf] +
                        (uint32_t)((wm + lrow) * SSTRIDE + kb + lcol) * 2;
                    ldsm4(addr, a[0], a[1], a[2], a[3]);
                }
                uint32_t bfr[2][4];
                #pragma unroll
                for (int nb = 0; nb < 2; nb++) {
                    uint32_t addr = smb[buf] +
                        (uint32_t)((64 + wn + nb * 16 + lrow) * SSTRIDE + kb + lcol) * 2;
                    ldsm4(addr, bfr[nb][0], bfr[nb][1], bfr[nb][2], bfr[nb][3]);
                }
                #pragma unroll
                for (int oct = 0; oct < 4; oct++) {
                    const int nb = oct >> 1, par = oct & 1;
                    mma16816(acc[oct], a, bfr[nb][par], bfr[nb][par + 2]);
                }
            }
            __syncthreads();
        }

        const int g = lane >> 2, t = lane & 3;
        #pragma unroll
        for (int oct = 0; oct < 4; oct++) {
            const int col = n0 + wn + oct * 8 + 2 * t;
            const float b0 = __ldg(bias + col), b1 = __ldg(bias + col + 1);
            const int r0 = m0 + wm + g;
            float2 v0 = { acc[oct][0] + b0, acc[oct][1] + b1 };
            float2 v1 = { acc[oct][2] + b0, acc[oct][3] + b1 };
            *(float2*)(g_P + (size_t)r0 * D_ + col)       = v0;
            *(float2*)(g_P + (size_t)(r0 + 8) * D_ + col) = v1;
        }
    } else {
        // ---------- FFMA2 path: R1 values via fma.rn.f32x2, rows 2048+ -----
        const int fi = grp * 3 + (sub - 4);            // 0..287
        const int m0 = MT_ROWS + (fi % (MF_ROWS / 64)) * 64;
        const int n0 = (fi / (MF_ROWS / 64)) * 64;

        float (*As)[64] = (float(*)[64])smraw;          // [16][64]
        float (*Bs)[64] = (float(*)[64])(smraw + 4096); // [16][64]

        const int tx = tid & 15, ty = tid >> 4;
        const int lrow = tid >> 2;
        const int kq   = (tid & 3) << 2;
        const int gr   = m0 + lrow;
        const float* xsrc = (gr < CROWS) ? (cdd + (size_t)gr * D_)
                         : (gr < ROWS)   ? (his + (size_t)(gr - CROWS) * D_)
                                         : his;
        const float* wsrc = W + (size_t)(n0 + lrow) * D_;

        unsigned long long acc2[4][2] = {};   // (j,j+1) packed pairs, zero = (0.f,0.f)

        for (int k0 = 0; k0 < D_; k0 += 16) {
            float4 a = *(const float4*)(xsrc + k0 + kq);
            float4 b = *(const float4*)(wsrc + k0 + kq);
            As[kq+0][lrow] = a.x; As[kq+1][lrow] = a.y;
            As[kq+2][lrow] = a.z; As[kq+3][lrow] = a.w;
            Bs[kq+0][lrow] = b.x; Bs[kq+1][lrow] = b.y;
            Bs[kq+2][lrow] = b.z; Bs[kq+3][lrow] = b.w;
            __syncthreads();

            #pragma unroll
            for (int kk = 0; kk < 16; kk++) {
                float4 av = *(const float4*)&As[kk][ty << 2];
                // reinterpret 4 floats as 2 packed f32x2 (low lane = lower col)
                const unsigned long long* bp =
                    (const unsigned long long*)&Bs[kk][tx << 2];
                unsigned long long b0 = bp[0], b1 = bp[1];
                float aa[4] = {av.x, av.y, av.z, av.w};
                #pragma unroll
                for (int i = 0; i < 4; i++) {
                    unsigned long long ai = dup_f32x2(aa[i]);
                    fma_f32x2(acc2[i][0], ai, b0);
                    fma_f32x2(acc2[i][1], ai, b1);
                }
            }
            __syncthreads();
        }

        #pragma unroll
        for (int i = 0; i < 4; i++) {
            const int r = m0 + (ty << 2) + i;
            #pragma unroll
            for (int jp = 0; jp < 2; jp++) {
                float2 v = unpack_f32x2(acc2[i][jp]);
                const int n = n0 + (tx << 2) + jp * 2;
                g_P[(size_t)r * D_ + n]     = v.x + bias[n];
                g_P[(size_t)r * D_ + n + 1] = v.y + bias[n + 1];
            }
        }
    }
}

// =============== compensated fp32 accumulation (TwoProd+TwoSum) ============
__device__ __forceinline__ void dot2_acc(float a, float b, float& s, float& c) {
    float p  = __fmul_rn(a, b);
    float e  = __fmaf_rn(a, b, -p);
    float t  = __fadd_rn(s, p);
    float bp = __fsub_rn(t, s);
    float e2 = __fadd_rn(__fsub_rn(s, __fsub_rn(t, bp)), __fsub_rn(p, bp));
    s = t;
    c = __fadd_rn(c, __fadd_rn(e, e2));
}

// ---------- 2+3) attention scores, block (b, part); ONE h per warp ---------
#define HSPLIT 5
#define HPER (H_ / HSPLIT)               // 10

__global__ void __launch_bounds__(320)
attn_score(const int* __restrict__ his_mask) {
    const int b    = blockIdx.x;
    const int part = blockIdx.y;
    const int tid = threadIdx.x;
    const int w = tid >> 5, l = tid & 31;

    __shared__ float  cand[C_][D_];      // 15 KB
    __shared__ double invc[C_];

    for (int i = tid; i < C_ * (D_ / 4); i += 320) {
        const int c = i / (D_ / 4), j = i % (D_ / 4);
        ((float4*)cand[c])[j] = ((const float4*)(g_P + (size_t)(b * C_ + c) * D_))[j];
    }
    __syncthreads();

    if (w < C_) {
        float s = 0.f, cc = 0.f;
        for (int k = l; k < D_; k += 32) { float v = cand[w][k]; dot2_acc(v, v, s, cc); }
        double d = (double)s + (double)cc;
        #pragma unroll
        for (int o = 16; o; o >>= 1) d += __shfl_down_sync(0xffffffffu, d, o);
        if (l == 0) invc[w] = 1.0 / fmax(sqrt(d), 1e-12);
    }
    __syncthreads();

    {
        const int h = part * HPER + w;   // one h per warp, w in 0..9
        const float4* ph = (const float4*)(g_P + (size_t)(CROWS + b * H_ + h) * D_);
        float s[C_] = {}, cc[C_] = {};
        float sn = 0.f, cn = 0.f;
        #pragma unroll
        for (int j = 0; j < D_ / 128; j++) {
            const int idx = l + 32 * j;
            const float4 v = ph[idx];
            dot2_acc(v.x, v.x, sn, cn); dot2_acc(v.y, v.y, sn, cn);
            dot2_acc(v.z, v.z, sn, cn); dot2_acc(v.w, v.w, sn, cn);
            #pragma unroll
            for (int c = 0; c < C_; c++) {
                const float4 cv = ((const float4*)cand[c])[idx];
                dot2_acc(v.x, cv.x, s[c], cc[c]); dot2_acc(v.y, cv.y, s[c], cc[c]);
                dot2_acc(v.z, cv.z, s[c], cc[c]); dot2_acc(v.w, cv.w, s[c], cc[c]);
            }
        }
        double dn = (double)sn + (double)cn;
        double dc[C_];
        #pragma unroll
        for (int c = 0; c < C_; c++) dc[c] = (double)s[c] + (double)cc[c];
        #pragma unroll
        for (int o = 16; o; o >>= 1) {
            dn += __shfl_down_sync(0xffffffffu, dn, o);
            #pragma unroll
            for (int c = 0; c < C_; c++) dc[c] += __shfl_down_sync(0xffffffffu, dc[c], o);
        }
        if (l == 0) {
            const bool valid = (his_mask[b * H_ + h] != 0) || (h < K_);
            const double invh = 1.0 / fmax(sqrt(dn), 1e-12);
            #pragma unroll
            for (int c = 0; c < C_; c++)
                g_attn[(b * C_ + c) * H_ + h] =
                    valid ? dc[c] * invc[c] * invh : -CUDART_INF;
        }
    }
}

// ---------------- 4) top-K (exact R1 kernel: one warp per (b,c)) -----------
__global__ void topk_kernel() {
    const int gw = (blockIdx.x * blockDim.x + threadIdx.x) >> 5;
    const int l  = threadIdx.x & 31;
    if (gw >= CROWS) return;
    const double* a = g_attn + (size_t)gw * H_;

    double v0 = (l      < H_) ? a[l]      : -CUDART_INF;
    double v1 = (l + 32 < H_) ? a[l + 32] : -CUDART_INF;
    bool used0 = false, used1 = false;

    for (int k = 0; k < K_; k++) {
        double bv = -CUDART_INF;
        int    bi = 1 << 30;
        if (!used1)                           { bv = v1; bi = l + 32; }
        if (!used0 && (used1 || v0 >= v1))    { bv = v0; bi = l; }
        #pragma unroll
        for (int o = 16; o; o >>= 1) {
            double ov = __shfl_down_sync(0xffffffffu, bv, o);
            int    oi = __shfl_down_sync(0xffffffffu, bi, o);
            if (ov > bv || (ov == bv && oi < bi)) { bv = ov; bi = oi; }
        }
        bi = __shfl_sync(0xffffffffu, bi, 0);
        if (l == 0) g_idx[gw * K_ + k] = bi;
        if (bi == l)      used0 = true;
        if (bi == l + 32) used1 = true;
    }
}

// ------- 5+6) embedding gather + fused mask gather (bandwidth-bound) -------
__global__ void gather_emb(const float* __restrict__ emb,
                           const int* __restrict__ am,
                           float* __restrict__ out) {
    const int sel  = blockIdx.x >> 3;
    const int part = blockIdx.x & 7;
    const int b    = sel / (C_ * K_);
    const int idx  = g_idx[sel];
    const float4* src = (const float4*)(emb + ((size_t)b * H_ + idx) * SE);
    float4*       dst = (float4*)(out + (size_t)sel * SE);
    const int base = part * 768;
    #pragma unroll
    for (int i = 0; i < 3; i++) {
        const int o = base + threadIdx.x + i * 256;
        __stcs(dst + o, src[o]);
    }
    if (part == 7 && threadIdx.x < S_) {
        float* outm = out + (size_t)SEL * SE;
        outm[sel * S_ + threadIdx.x] =
            (float)am[((size_t)b * H_ + idx) * S_ + threadIdx.x];
    }
}

// ---------------------------------------------------------------------------
extern "C" void kernel_launch(void* const* d_in, const int* in_sizes, int n_in,
                              void* d_out, int out_size) {
    const float* cdd  = (const float*)d_in[0];   // [B,C,D]
    const float* his  = (const float*)d_in[1];   // [B,H,D]
    const float* emb  = (const float*)d_in[2];   // [B,H,S,E]
    const int*   am   = (const int*)  d_in[3];   // [B,H,S]
    const int*   hm   = (const int*)  d_in[4];   // [B,H,1]
    const float* W    = (const float*)d_in[5];   // [D,D]
    const float* bias = (const float*)d_in[6];   // [D]
    float* out = (float*)d_out;

    const size_t NX4 = (size_t)MT_ROWS * D_ / 4;
    const size_t NW4 = (size_t)D_ * D_ / 4;
    splitX_kernel<<<(unsigned)((NX4 + 255) / 256), 256>>>(cdd, his);
    splitW_kernel<<<(unsigned)((NW4 + 255) / 256), 256>>>(W);
    gemm_hybrid<<<NCTA_ALL, 256>>>(cdd, his, W, bias);
    attn_score<<<dim3(B_, HSPLIT), 320>>>(hm);
    topk_kernel<<<(CROWS * 32 + 255) / 256, 256>>>();
    gather_emb<<<SEL * 8, 256>>>(emb, am, out);
}

// round 16
// speedup vs baseline: 1.2010x; 1.1996x over previous
#include <cuda_runtime.h>
#include <math.h>
#include <math_constants.h>
#include <cstdint>

// Problem shapes (fixed by the dataset)
#define B_ 64
#define C_ 5
#define H_ 50
#define S_ 32
#define E_ 768
#define D_ 768
#define K_ 5
#define CROWS (B_*C_)            // 320 candidate rows
#define HROWS (B_*H_)            // 3200 history rows
#define ROWS (CROWS + HROWS)     // 3520 total projected rows
#define ROWSP 3584               // padded to multiple of 64
#define SEL (CROWS*K_)           // 1600 gather selections
#define SE (S_*E_)               // 24576 floats per selection

// ---------------- scratch (static device globals; no allocation) -----------
__device__ float  g_P[(size_t)ROWSP * D_];               // projected rows (padded)
__device__ double g_attn[CROWS * H_];                    // masked attention scores
__device__ int    g_idx[SEL];                            // top-K indices per (b,c)

// ======================= packed f32x2 helpers (sm_10x) =====================
// componentwise round-to-nearest FMA — values bit-identical to scalar fmaf
__device__ __forceinline__ unsigned long long dup_f32x2(float x) {
    unsigned long long r;
    asm("mov.b64 %0, {%1, %1};" : "=l"(r) : "f"(x));
    return r;
}
__device__ __forceinline__ void fma_f32x2(unsigned long long& acc,
                                          unsigned long long a,
                                          unsigned long long b) {
    asm("fma.rn.f32x2 %0, %1, %2, %0;" : "+l"(acc) : "l"(a), "l"(b));
}
__device__ __forceinline__ float2 unpack_f32x2(unsigned long long v) {
    float2 r;
    asm("mov.b64 {%0, %1}, %2;" : "=f"(r.x), "=f"(r.y) : "l"(v));
    return r;
}

// ============ 1) pure FFMA2 SGEMM: P = X·Wᵀ + b  (exact fp32) ==============
// 64x64 tile, 64 threads, 8x8 microtile (4 MAC per smem float), BK=16.
// Accumulation k-ascending, componentwise rn FMA == R1's proven fmaf chain.
#define BK 16
#define TM 64
#define TN 64
#define MT (ROWSP / TM)            // 56
#define NT (D_ / TN)               // 12
#define NCTA (MT * NT)             // 672

__global__ void __launch_bounds__(64, 8)
gemm_ffma2(const float* __restrict__ cdd, const float* __restrict__ his,
           const float* __restrict__ W, const float* __restrict__ bias) {
    __shared__ float As[BK][TM];   // k-major
    __shared__ float Bs[BK][TN];

    const int tid = threadIdx.x;               // 64 threads
    const int m0  = (blockIdx.x % MT) * TM;
    const int n0  = (blockIdx.x / MT) * TN;
    const int tx  = tid & 7;                   // n micro (8)
    const int ty  = tid >> 3;                  // m micro (8)

    // loader: kq = (tid&3)*4 ; row = (tid>>2) + 16*i, i=0..3
    const int kq    = (tid & 3) << 2;
    const int rbase = tid >> 2;                // 0..15

    // row source pointers (4 rows for A)
    const float* xsrc[4];
    #pragma unroll
    for (int i = 0; i < 4; i++) {
        const int gr = m0 + rbase + 16 * i;
        xsrc[i] = (gr < CROWS) ? (cdd + (size_t)gr * D_)
                : (gr < ROWS)  ? (his + (size_t)(gr - CROWS) * D_)
                               : his;          // pad rows: any valid mem
    }
    const float* wsrc[4];
    #pragma unroll
    for (int i = 0; i < 4; i++)
        wsrc[i] = W + (size_t)(n0 + rbase + 16 * i) * D_;

    unsigned long long acc2[8][4] = {};        // rows ty*8+i, col pairs tx*8+2jp

    for (int k0 = 0; k0 < D_; k0 += BK) {
        #pragma unroll
        for (int i = 0; i < 4; i++) {
            const int row = rbase + 16 * i;
            float4 a = *(const float4*)(xsrc[i] + k0 + kq);
            float4 b = *(const float4*)(wsrc[i] + k0 + kq);
            As[kq+0][row] = a.x; As[kq+1][row] = a.y;
            As[kq+2][row] = a.z; As[kq+3][row] = a.w;
            Bs[kq+0][row] = b.x; Bs[kq+1][row] = b.y;
            Bs[kq+2][row] = b.z; Bs[kq+3][row] = b.w;
        }
        __syncthreads();

        #pragma unroll
        for (int kk = 0; kk < BK; kk++) {
            float4 a0 = *(const float4*)&As[kk][ty << 3];
            float4 a1 = *(const float4*)&As[kk][(ty << 3) + 4];
            const unsigned long long* bp =
                (const unsigned long long*)&Bs[kk][tx << 3];
            unsigned long long b0 = bp[0], b1 = bp[1], b2 = bp[2], b3 = bp[3];
            float aa[8] = {a0.x, a0.y, a0.z, a0.w, a1.x, a1.y, a1.z, a1.w};
            #pragma unroll
            for (int i = 0; i < 8; i++) {
                unsigned long long ai = dup_f32x2(aa[i]);
                fma_f32x2(acc2[i][0], ai, b0);
                fma_f32x2(acc2[i][1], ai, b1);
                fma_f32x2(acc2[i][2], ai, b2);
                fma_f32x2(acc2[i][3], ai, b3);
            }
        }
        __syncthreads();
    }

    #pragma unroll
    for (int i = 0; i < 8; i++) {
        const int r = m0 + (ty << 3) + i;
        #pragma unroll
        for (int jp = 0; jp < 4; jp++) {
            float2 v = unpack_f32x2(acc2[i][jp]);
            const int n = n0 + (tx << 3) + jp * 2;
            float2 o = { v.x + bias[n], v.y + bias[n + 1] };
            *(float2*)(g_P + (size_t)r * D_ + n) = o;
        }
    }
}

// =============== compensated fp32 accumulation (TwoProd+TwoSum) ============
__device__ __forceinline__ void dot2_acc(float a, float b, float& s, float& c) {
    float p  = __fmul_rn(a, b);
    float e  = __fmaf_rn(a, b, -p);
    float t  = __fadd_rn(s, p);
    float bp = __fsub_rn(t, s);
    float e2 = __fadd_rn(__fsub_rn(s, __fsub_rn(t, bp)), __fsub_rn(p, bp));
    s = t;
    c = __fadd_rn(c, __fadd_rn(e, e2));
}

// ---------- 2+3) attention scores, block (b, part); ONE h per warp ---------
// Byte-identical to R14 (measured 32.3us).
#define HSPLIT 5
#define HPER (H_ / HSPLIT)               // 10

__global__ void __launch_bounds__(320)
attn_score(const int* __restrict__ his_mask) {
    const int b    = blockIdx.x;
    const int part = blockIdx.y;
    const int tid = threadIdx.x;
    const int w = tid >> 5, l = tid & 31;

    __shared__ float  cand[C_][D_];      // 15 KB
    __shared__ double invc[C_];

    for (int i = tid; i < C_ * (D_ / 4); i += 320) {
        const int c = i / (D_ / 4), j = i % (D_ / 4);
        ((float4*)cand[c])[j] = ((const float4*)(g_P + (size_t)(b * C_ + c) * D_))[j];
    }
    __syncthreads();

    if (w < C_) {
        float s = 0.f, cc = 0.f;
        for (int k = l; k < D_; k += 32) { float v = cand[w][k]; dot2_acc(v, v, s, cc); }
        double d = (double)s + (double)cc;
        #pragma unroll
        for (int o = 16; o; o >>= 1) d += __shfl_down_sync(0xffffffffu, d, o);
        if (l == 0) invc[w] = 1.0 / fmax(sqrt(d), 1e-12);
    }
    __syncthreads();

    {
        const int h = part * HPER + w;   // one h per warp, w in 0..9
        const float4* ph = (const float4*)(g_P + (size_t)(CROWS + b * H_ + h) * D_);
        float s[C_] = {}, cc[C_] = {};
        float sn = 0.f, cn = 0.f;
        #pragma unroll
        for (int j = 0; j < D_ / 128; j++) {
            const int idx = l + 32 * j;
            const float4 v = ph[idx];
            dot2_acc(v.x, v.x, sn, cn); dot2_acc(v.y, v.y, sn, cn);
            dot2_acc(v.z, v.z, sn, cn); dot2_acc(v.w, v.w, sn, cn);
            #pragma unroll
            for (int c = 0; c < C_; c++) {
                const float4 cv = ((const float4*)cand[c])[idx];
                dot2_acc(v.x, cv.x, s[c], cc[c]); dot2_acc(v.y, cv.y, s[c], cc[c]);
                dot2_acc(v.z, cv.z, s[c], cc[c]); dot2_acc(v.w, cv.w, s[c], cc[c]);
            }
        }
        double dn = (double)sn + (double)cn;
        double dc[C_];
        #pragma unroll
        for (int c = 0; c < C_; c++) dc[c] = (double)s[c] + (double)cc[c];
        #pragma unroll
        for (int o = 16; o; o >>= 1) {
            dn += __shfl_down_sync(0xffffffffu, dn, o);
            #pragma unroll
            for (int c = 0; c < C_; c++) dc[c] += __shfl_down_sync(0xffffffffu, dc[c], o);
        }
        if (l == 0) {
            const bool valid = (his_mask[b * H_ + h] != 0) || (h < K_);
            const double invh = 1.0 / fmax(sqrt(dn), 1e-12);
            #pragma unroll
            for (int c = 0; c < C_; c++)
                g_attn[(b * C_ + c) * H_ + h] =
                    valid ? dc[c] * invc[c] * invh : -CUDART_INF;
        }
    }
}

// ---------------- 4) top-K (exact R1 kernel: one warp per (b,c)) -----------
__global__ void topk_kernel() {
    const int gw = (blockIdx.x * blockDim.x + threadIdx.x) >> 5;
    const int l  = threadIdx.x & 31;
    if (gw >= CROWS) return;
    const double* a = g_attn + (size_t)gw * H_;

    double v0 = (l      < H_) ? a[l]      : -CUDART_INF;
    double v1 = (l + 32 < H_) ? a[l + 32] : -CUDART_INF;
    bool used0 = false, used1 = false;

    for (int k = 0; k < K_; k++) {
        double bv = -CUDART_INF;
        int    bi = 1 << 30;
        if (!used1)                           { bv = v1; bi = l + 32; }
        if (!used0 && (used1 || v0 >= v1))    { bv = v0; bi = l; }
        #pragma unroll
        for (int o = 16; o; o >>= 1) {
            double ov = __shfl_down_sync(0xffffffffu, bv, o);
            int    oi = __shfl_down_sync(0xffffffffu, bi, o);
            if (ov > bv || (ov == bv && oi < bi)) { bv = ov; bi = oi; }
        }
        bi = __shfl_sync(0xffffffffu, bi, 0);
        if (l == 0) g_idx[gw * K_ + k] = bi;
        if (bi == l)      used0 = true;
        if (bi == l + 32) used1 = true;
    }
}

// ------- 5+6) embedding gather + fused mask gather (bandwidth-bound) -------
__global__ void gather_emb(const float* __restrict__ emb,
                           const int* __restrict__ am,
                           float* __restrict__ out) {
    const int sel  = blockIdx.x >> 3;
    const int part = blockIdx.x & 7;
    const int b    = sel / (C_ * K_);
    const int idx  = g_idx[sel];
    const float4* src = (const float4*)(emb + ((size_t)b * H_ + idx) * SE);
    float4*       dst = (float4*)(out + (size_t)sel * SE);
    const int base = part * 768;
    #pragma unroll
    for (int i = 0; i < 3; i++) {
        const int o = base + threadIdx.x + i * 256;
        __stcs(dst + o, src[o]);
    }
    if (part == 7 && threadIdx.x < S_) {
        float* outm = out + (size_t)SEL * SE;
        outm[sel * S_ + threadIdx.x] =
            (float)am[((size_t)b * H_ + idx) * S_ + threadIdx.x];
    }
}

// ---------------------------------------------------------------------------
extern "C" void kernel_launch(void* const* d_in, const int* in_sizes, int n_in,
                              void* d_out, int out_size) {
    const float* cdd  = (const float*)d_in[0];   // [B,C,D]
    const float* his  = (const float*)d_in[1];   // [B,H,D]
    const float* emb  = (const float*)d_in[2];   // [B,H,S,E]
    const int*   am   = (const int*)  d_in[3];   // [B,H,S]
    const int*   hm   = (const int*)  d_in[4];   // [B,H,1]
    const float* W    = (const float*)d_in[5];   // [D,D]
    const float* bias = (const float*)d_in[6];   // [D]
    float* out = (float*)d_out;

    gemm_ffma2<<<NCTA, 64>>>(cdd, his, W, bias);
    attn_score<<<dim3(B_, HSPLIT), 320>>>(hm);
    topk_kernel<<<(CROWS * 32 + 255) / 256, 256>>>();
    gather_emb<<<SEL * 8, 256>>>(emb, am, out);
}

// round 17
// speedup vs baseline: 1.2900x; 1.0741x over previous
#include <cuda_runtime.h>
#include <math.h>
#include <math_constants.h>
#include <cstdint>

// Problem shapes (fixed by the dataset)
#define B_ 64
#define C_ 5
#define H_ 50
#define S_ 32
#define E_ 768
#define D_ 768
#define K_ 5
#define CROWS (B_*C_)            // 320 candidate rows
#define HROWS (B_*H_)            // 3200 history rows
#define ROWS (CROWS + HROWS)     // 3520 total projected rows
#define ROWSP 3584               // padded to multiple of 64
#define SEL (CROWS*K_)           // 1600 gather selections
#define SE (S_*E_)               // 24576 floats per selection

typedef unsigned long long ull;

// ---------------- scratch (static device globals; no allocation) -----------
__device__ float  g_Xt[(size_t)D_ * ROWSP];              // X transposed [k][m]
__device__ float  g_Wt[(size_t)D_ * D_];                 // W transposed [k][n]
__device__ float  g_P[(size_t)ROWSP * D_];               // projected rows (padded)
__device__ double g_attn[CROWS * H_];                    // masked attention scores
__device__ int    g_idx[SEL];                            // top-K indices per (b,c)

// ======================= packed f32x2 helpers (sm_10x) =====================
// componentwise round-to-nearest ops — values bit-identical to scalar fp32
__device__ __forceinline__ ull dup_f32x2(float x) {
    ull r; asm("mov.b64 %0, {%1, %1};" : "=l"(r) : "f"(x)); return r;
}
__device__ __forceinline__ void fma_f32x2(ull& acc, ull a, ull b) {
    asm("fma.rn.f32x2 %0, %1, %2, %0;" : "+l"(acc) : "l"(a), "l"(b));
}
__device__ __forceinline__ ull fma3_f32x2(ull a, ull b, ull c) {
    ull r; asm("fma.rn.f32x2 %0, %1, %2, %3;" : "=l"(r) : "l"(a), "l"(b), "l"(c)); return r;
}
__device__ __forceinline__ ull mul_f32x2(ull a, ull b) {
    ull r; asm("mul.rn.f32x2 %0, %1, %2;" : "=l"(r) : "l"(a), "l"(b)); return r;
}
__device__ __forceinline__ ull add_f32x2(ull a, ull b) {
    ull r; asm("add.rn.f32x2 %0, %1, %2;" : "=l"(r) : "l"(a), "l"(b)); return r;
}
__device__ __forceinline__ ull sub_f32x2(ull a, ull b) {
    ull r; asm("sub.rn.f32x2 %0, %1, %2;" : "=l"(r) : "l"(a), "l"(b)); return r;
}
__device__ __forceinline__ ull neg_f32x2(ull a) { return a ^ 0x8000000080000000ULL; }
__device__ __forceinline__ float2 unpack_f32x2(ull v) {
    float2 r; asm("mov.b64 {%0, %1}, %2;" : "=f"(r.x), "=f"(r.y) : "l"(v)); return r;
}

__device__ __forceinline__ uint32_t smem_u32(const void* p) {
    uint32_t a;
    asm("{ .reg .u64 t; cvta.to.shared.u64 t, %1; cvt.u32.u64 %0, t; }" : "=r"(a) : "l"(p));
    return a;
}
__device__ __forceinline__ void cp_async16(uint32_t dst, const void* src) {
    asm volatile("cp.async.cg.shared.global [%0], [%1], 16;"
                 :: "r"(dst), "l"(__cvta_generic_to_global(src)));
}
#define CP_COMMIT() asm volatile("cp.async.commit_group;" ::: "memory")
#define CP_WAIT(n)  asm volatile("cp.async.wait_group %0;" :: "n"(n) : "memory")

// ================== 0) transposes (pure copies, no arithmetic) =============
__global__ void transpose_X(const float* __restrict__ cdd,
                            const float* __restrict__ his) {
    __shared__ float t[32][33];
    const int m0 = blockIdx.x * 32, k0 = blockIdx.y * 32;
    const int tx = threadIdx.x, ty = threadIdx.y;   // 32 x 8
    #pragma unroll
    for (int i = ty; i < 32; i += 8) {
        const int m = m0 + i, k = k0 + tx;
        float v = 0.f;
        if (m < CROWS)      v = cdd[(size_t)m * D_ + k];
        else if (m < ROWS)  v = his[(size_t)(m - CROWS) * D_ + k];
        t[i][tx] = v;
    }
    __syncthreads();
    #pragma unroll
    for (int i = ty; i < 32; i += 8)
        g_Xt[(size_t)(k0 + i) * ROWSP + m0 + tx] = t[tx][i];
}

__global__ void transpose_W(const float* __restrict__ W) {
    __shared__ float t[32][33];
    const int n0 = blockIdx.x * 32, k0 = blockIdx.y * 32;
    const int tx = threadIdx.x, ty = threadIdx.y;
    #pragma unroll
    for (int i = ty; i < 32; i += 8)
        t[i][tx] = W[(size_t)(n0 + i) * D_ + k0 + tx];
    __syncthreads();
    #pragma unroll
    for (int i = ty; i < 32; i += 8)
        g_Wt[(size_t)(k0 + i) * D_ + n0 + tx] = t[tx][i];
}

// ============ 1) FFMA2 SGEMM, cp.async double-buffered =====================
// Inner compute bit-identical to R15 (same As/Bs contents, same FFMA2 order).
#define BK 16
#define TM 64
#define TN 64
#define MT (ROWSP / TM)            // 56
#define NT (D_ / TN)               // 12
#define NCTA (MT * NT)             // 672
#define NK0 (D_ / BK)              // 48

__global__ void __launch_bounds__(64, 8)
gemm_ffma2(const float* __restrict__ bias) {
    __shared__ float As[2][BK][TM];   // k-major, filled by cp.async (no transpose)
    __shared__ float Bs[2][BK][TN];

    const int tid = threadIdx.x;               // 64 threads
    const int m0  = (blockIdx.x % MT) * TM;
    const int n0  = (blockIdx.x / MT) * TN;
    const int tx  = tid & 7;
    const int ty  = tid >> 3;

    const uint32_t sa[2] = { smem_u32(&As[0][0][0]), smem_u32(&As[1][0][0]) };
    const uint32_t sb[2] = { smem_u32(&Bs[0][0][0]), smem_u32(&Bs[1][0][0]) };

    auto load_stage = [&](int it, int buf) {
        const int k0 = it * BK;
        #pragma unroll
        for (int i = 0; i < 4; i++) {
            const int c   = tid + 64 * i;       // 0..255
            const int row = c >> 4;             // 0..15
            const int col = (c & 15) * 4;       // 0..60
            cp_async16(sa[buf] + (uint32_t)(row * TM + col) * 4,
                       g_Xt + (size_t)(k0 + row) * ROWSP + m0 + col);
            cp_async16(sb[buf] + (uint32_t)(row * TN + col) * 4,
                       g_Wt + (size_t)(k0 + row) * D_ + n0 + col);
        }
        CP_COMMIT();
    };

    ull acc2[8][4] = {};

    load_stage(0, 0);

    for (int it = 0; it < NK0; it++) {
        const int buf = it & 1;
        if (it + 1 < NK0) { load_stage(it + 1, buf ^ 1); CP_WAIT(1); }
        else              { CP_WAIT(0); }
        __syncthreads();

        #pragma unroll
        for (int kk = 0; kk < BK; kk++) {
            float4 a0 = *(const float4*)&As[buf][kk][ty << 3];
            float4 a1 = *(const float4*)&As[buf][kk][(ty << 3) + 4];
            const ull* bp = (const ull*)&Bs[buf][kk][tx << 3];
            ull b0 = bp[0], b1 = bp[1], b2 = bp[2], b3 = bp[3];
            float aa[8] = {a0.x, a0.y, a0.z, a0.w, a1.x, a1.y, a1.z, a1.w};
            #pragma unroll
            for (int i = 0; i < 8; i++) {
                ull ai = dup_f32x2(aa[i]);
                fma_f32x2(acc2[i][0], ai, b0);
                fma_f32x2(acc2[i][1], ai, b1);
                fma_f32x2(acc2[i][2], ai, b2);
                fma_f32x2(acc2[i][3], ai, b3);
            }
        }
        __syncthreads();
    }

    #pragma unroll
    for (int i = 0; i < 8; i++) {
        const int r = m0 + (ty << 3) + i;
        #pragma unroll
        for (int jp = 0; jp < 4; jp++) {
            float2 v = unpack_f32x2(acc2[i][jp]);
            const int n = n0 + (tx << 3) + jp * 2;
            float2 o = { v.x + bias[n], v.y + bias[n + 1] };
            *(float2*)(g_P + (size_t)r * D_ + n) = o;
        }
    }
}

// =============== packed compensated accumulation (TwoProd+TwoSum) ==========
__device__ __forceinline__ void dot2p(ull a, ull b, ull& s, ull& c) {
    ull p  = mul_f32x2(a, b);
    ull e  = fma3_f32x2(a, b, neg_f32x2(p));
    ull t  = add_f32x2(s, p);
    ull bp = sub_f32x2(t, s);
    ull e2 = add_f32x2(sub_f32x2(s, sub_f32x2(t, bp)), sub_f32x2(p, bp));
    s = t;
    c = add_f32x2(c, add_f32x2(e, e2));
}
__device__ __forceinline__ double comb2(ull s, ull c) {
    float2 sv = unpack_f32x2(s), cv = unpack_f32x2(c);
    return ((double)sv.x + (double)sv.y) + ((double)cv.x + (double)cv.y);
}

// ---------- 2+3) attention scores, block (b, part); ONE h per warp ---------
// Packed f32x2 compensated chains (even/odd lanes); ~1e-14 accuracy.
#define HSPLIT 5
#define HPER (H_ / HSPLIT)               // 10
#define D2 (D_ / 2)                      // 384 packed pairs per row

__global__ void __launch_bounds__(320)
attn_score(const int* __restrict__ his_mask) {
    const int b    = blockIdx.x;
    const int part = blockIdx.y;
    const int tid = threadIdx.x;
    const int w = tid >> 5, l = tid & 31;

    __shared__ float  cand[C_][D_];      // 15 KB
    __shared__ double invc[C_];

    for (int i = tid; i < C_ * (D_ / 4); i += 320) {
        const int c = i / (D_ / 4), j = i % (D_ / 4);
        ((float4*)cand[c])[j] = ((const float4*)(g_P + (size_t)(b * C_ + c) * D_))[j];
    }
    __syncthreads();

    if (w < C_) {
        ull s = 0, cc = 0;
        const ull* cp = (const ull*)cand[w];
        for (int k = l; k < D2; k += 32) { ull v = cp[k]; dot2p(v, v, s, cc); }
        double d = comb2(s, cc);
        #pragma unroll
        for (int o = 16; o; o >>= 1) d += __shfl_down_sync(0xffffffffu, d, o);
        if (l == 0) invc[w] = 1.0 / fmax(sqrt(d), 1e-12);
    }
    __syncthreads();

    {
        const int h = part * HPER + w;   // one h per warp, w in 0..9
        const ull* ph = (const ull*)(g_P + (size_t)(CROWS + b * H_ + h) * D_);
        ull s[C_] = {}, cc[C_] = {};
        ull sn = 0, cn = 0;
        #pragma unroll
        for (int j = 0; j < D2 / 64; j++) {      // 6 iters: 2 pairs per lane
            const int idx = 2 * l + 64 * j;
            const ull v0 = ph[idx], v1 = ph[idx + 1];
            dot2p(v0, v0, sn, cn); dot2p(v1, v1, sn, cn);
            #pragma unroll
            for (int c = 0; c < C_; c++) {
                const ull* cp = (const ull*)cand[c];
                dot2p(v0, cp[idx], s[c], cc[c]);
                dot2p(v1, cp[idx + 1], s[c], cc[c]);
            }
        }
        double dn = comb2(sn, cn);
        double dc[C_];
        #pragma unroll
        for (int c = 0; c < C_; c++) dc[c] = comb2(s[c], cc[c]);
        #pragma unroll
        for (int o = 16; o; o >>= 1) {
            dn += __shfl_down_sync(0xffffffffu, dn, o);
            #pragma unroll
            for (int c = 0; c < C_; c++) dc[c] += __shfl_down_sync(0xffffffffu, dc[c], o);
        }
        if (l == 0) {
            const bool valid = (his_mask[b * H_ + h] != 0) || (h < K_);
            const double invh = 1.0 / fmax(sqrt(dn), 1e-12);
            #pragma unroll
            for (int c = 0; c < C_; c++)
                g_attn[(b * C_ + c) * H_ + h] =
                    valid ? dc[c] * invc[c] * invh : -CUDART_INF;
        }
    }
}

// ---------------- 4) top-K (exact R1 kernel: one warp per (b,c)) -----------
__global__ void topk_kernel() {
    const int gw = (blockIdx.x * blockDim.x + threadIdx.x) >> 5;
    const int l  = threadIdx.x & 31;
    if (gw >= CROWS) return;
    const double* a = g_attn + (size_t)gw * H_;

    double v0 = (l      < H_) ? a[l]      : -CUDART_INF;
    double v1 = (l + 32 < H_) ? a[l + 32] : -CUDART_INF;
    bool used0 = false, used1 = false;

    for (int k = 0; k < K_; k++) {
        double bv = -CUDART_INF;
        int    bi = 1 << 30;
        if (!used1)                           { bv = v1; bi = l + 32; }
        if (!used0 && (used1 || v0 >= v1))    { bv = v0; bi = l; }
        #pragma unroll
        for (int o = 16; o; o >>= 1) {
            double ov = __shfl_down_sync(0xffffffffu, bv, o);
            int    oi = __shfl_down_sync(0xffffffffu, bi, o);
            if (ov > bv || (ov == bv && oi < bi)) { bv = ov; bi = oi; }
        }
        bi = __shfl_sync(0xffffffffu, bi, 0);
        if (l == 0) g_idx[gw * K_ + k] = bi;
        if (bi == l)      used0 = true;
        if (bi == l + 32) used1 = true;
    }
}

// ------- 5+6) embedding gather + fused mask gather (bandwidth-bound) -------
__global__ void gather_emb(const float* __restrict__ emb,
                           const int* __restrict__ am,
                           float* __restrict__ out) {
    const int sel  = blockIdx.x >> 3;
    const int part = blockIdx.x & 7;
    const int b    = sel / (C_ * K_);
    const int idx  = g_idx[sel];
    const float4* src = (const float4*)(emb + ((size_t)b * H_ + idx) * SE);
    float4*       dst = (float4*)(out + (size_t)sel * SE);
    const int base = part * 768;
    #pragma unroll
    for (int i = 0; i < 3; i++) {
        const int o = base + threadIdx.x + i * 256;
        __stcs(dst + o, src[o]);
    }
    if (part == 7 && threadIdx.x < S_) {
        float* outm = out + (size_t)SEL * SE;
        outm[sel * S_ + threadIdx.x] =
            (float)am[((size_t)b * H_ + idx) * S_ + threadIdx.x];
    }
}

// ---------------------------------------------------------------------------
extern "C" void kernel_launch(void* const* d_in, const int* in_sizes, int n_in,
                              void* d_out, int out_size) {
    const float* cdd  = (const float*)d_in[0];   // [B,C,D]
    const float* his  = (const float*)d_in[1];   // [B,H,D]
    const float* emb  = (const float*)d_in[2];   // [B,H,S,E]
    const int*   am   = (const int*)  d_in[3];   // [B,H,S]
    const int*   hm   = (const int*)  d_in[4];   // [B,H,1]
    const float* W    = (const float*)d_in[5];   // [D,D]
    const float* bias = (const float*)d_in[6];   // [D]
    float* out = (float*)d_out;

    transpose_X<<<dim3(ROWSP / 32, D_ / 32), dim3(32, 8)>>>(cdd, his);
    transpose_W<<<dim3(D_ / 32, D_ / 32), dim3(32, 8)>>>(W);
    gemm_ffma2<<<NCTA, 64>>>(bias);
    attn_score<<<dim3(B_, HSPLIT), 320>>>(hm);
    topk_kernel<<<(CROWS * 32 + 255) / 256, 256>>>();
    gather_emb<<<SEL * 8, 256>>>(emb, am, out);
}